// round 11
// baseline (speedup 1.0000x reference)
#include <cuda_runtime.h>
#include <cuda_bf16.h>
#include <math.h>
#include <stdint.h>

#define Bq 16
#define CIN 32
#define CCOND 100
#define LC 512
#define HOP 8
#define HID 64
#define NL 4
#define COUT 64
#define TT 4096
#define KD 192          // 64*3 features for the k=3 conv-as-GEMM
#define NLAY 6144       // CIN*COUT*3 = per-layer kernel channels
#define SLOPE 0.2f

// ---------------- scratch (static __device__, no allocations) ----------------
__device__ float d_h[Bq * HID * LC];
__device__ float d_tmp[Bq * HID * LC];
__device__ float d_A[Bq * LC * KD];                    // im2col of h (fp32, for kbias)
__device__ __align__(16) __nv_bfloat16 d_Ah[Bq * LC * KD];
__device__ __align__(16) __nv_bfloat16 d_Al[Bq * LC * KD];
__device__ __align__(16) __nv_bfloat16 d_Wh4[NL * NLAY * KD];
__device__ __align__(16) __nv_bfloat16 d_Wl4[NL * NLAY * KD];
__device__ float d_kern[(size_t)Bq * LC * NLAY];       // per-layer slice [m][ci][o][k] (~201MB)
__device__ float d_kbias[Bq * LC * NL * COUT];         // [m][layer][o]
__device__ float d_xx0[Bq * CIN * TT];
__device__ float d_xx1[Bq * CIN * TT];

__device__ __forceinline__ float lrelu(float v) { return v >= 0.f ? v : SLOPE * v; }

// ---------------- kernel predictor: input conv (k=5, pad=2) + lrelu, 4 outputs/thread ----------------
__global__ void conv_in_k(const float* __restrict__ c, const float* __restrict__ w,
                          const float* __restrict__ b) {
    int co = blockIdx.x, bb = blockIdx.y;
    int l0 = threadIdx.x * 4;                     // 128 threads
    const float* cb = c + (size_t)bb * CCOND * LC;
    const float* wr = w + co * CCOND * 5;
    float a0, a1, a2, a3;
    a0 = a1 = a2 = a3 = b[co];
    for (int ci = 0; ci < CCOND; ci++) {
        const float* cr = cb + ci * LC;
        float4 xm = *(const float4*)(cr + l0);
        float xm2 = (l0 >= 2) ? cr[l0 - 2] : 0.f;
        float xm1 = (l0 >= 1) ? cr[l0 - 1] : 0.f;
        float xp4 = (l0 + 4 < LC) ? cr[l0 + 4] : 0.f;
        float xp5 = (l0 + 5 < LC) ? cr[l0 + 5] : 0.f;
        float w0 = wr[ci * 5], w1 = wr[ci * 5 + 1], w2 = wr[ci * 5 + 2],
              w3 = wr[ci * 5 + 3], w4 = wr[ci * 5 + 4];
        a0 += xm2 * w0 + xm1 * w1 + xm.x * w2 + xm.y * w3 + xm.z * w4;
        a1 += xm1 * w0 + xm.x * w1 + xm.y * w2 + xm.z * w3 + xm.w * w4;
        a2 += xm.x * w0 + xm.y * w1 + xm.z * w2 + xm.w * w3 + xp4 * w4;
        a3 += xm.y * w0 + xm.z * w1 + xm.w * w2 + xp4 * w3 + xp5 * w4;
    }
    float4 o = {lrelu(a0), lrelu(a1), lrelu(a2), lrelu(a3)};
    *(float4*)(d_h + ((size_t)bb * HID + co) * LC + l0) = o;
}

// ---------------- fused residual block: out = in + lrelu(conv2(lrelu(conv1(in)))) ----------------
// one block per (64-pos tile, batch). srcH=1 -> d_h->d_tmp, srcH=0 -> d_tmp->d_h
#define RT 64
__global__ void __launch_bounds__(256) res_fused_k(const float* __restrict__ w0,
                                                   const float* __restrict__ b0,
                                                   const float* __restrict__ w1,
                                                   const float* __restrict__ b1,
                                                   int srcH) {
    __shared__ float s_in[HID][RT + 4];    // positions l0-2 .. l0+65
    __shared__ float s_r1[HID][RT + 4];    // r1 at l0-1 .. l0+64 (66 used)
    int lt = blockIdx.x, bb = blockIdx.y, tid = threadIdx.x;
    int l0 = lt * RT;
    const float* in = srcH ? d_h : d_tmp;
    float* out = srcH ? d_tmp : d_h;
    const float* ib = in + (size_t)bb * HID * LC;

    for (int v = tid; v < HID * (RT + 4); v += 256) {
        int ch = v / (RT + 4), p = v % (RT + 4);
        int t = l0 - 2 + p;
        s_in[ch][p] = (t >= 0 && t < LC) ? ib[ch * LC + t] : 0.f;
    }
    __syncthreads();
    // r1 at 66 positions (l0-1+p); ZERO outside [0, LC) (conv2 zero-pads r)
    for (int v = tid; v < HID * (RT + 2); v += 256) {
        int ch = v / (RT + 2), p = v % (RT + 2);
        int gpos = l0 - 1 + p;
        float acc = b0[ch];
        const float* wr = w0 + ch * HID * 3;
        for (int ci = 0; ci < HID; ci++)
            acc += s_in[ci][p] * wr[ci * 3] + s_in[ci][p + 1] * wr[ci * 3 + 1]
                 + s_in[ci][p + 2] * wr[ci * 3 + 2];
        s_r1[ch][p] = (gpos >= 0 && gpos < LC) ? lrelu(acc) : 0.f;
    }
    __syncthreads();
    for (int v = tid; v < HID * RT; v += 256) {
        int ch = v / RT, p = v % RT;
        float acc = b1[ch];
        const float* wr = w1 + ch * HID * 3;
        for (int ci = 0; ci < HID; ci++)
            acc += s_r1[ci][p] * wr[ci * 3] + s_r1[ci][p + 1] * wr[ci * 3 + 1]
                 + s_r1[ci][p + 2] * wr[ci * 3 + 2];
        out[(size_t)(bb * HID + ch) * LC + l0 + p] = lrelu(acc) + s_in[ch][p + 2];
    }
}

// ---------------- prep: im2col + A hi/lo split (from d_tmp) + all-layer W hi/lo split ----------------
__global__ void prep_k(const float* __restrict__ ker_w) {
    int b = blockIdx.x, tid = threadIdx.x;
    if (b < Bq * LC) {
        if (tid < KD) {
            int m = b, bb = m / LC, l = m % LC;
            int c2 = tid / 3, kk = tid % 3;
            int t = l + kk - 1;
            float v = (t >= 0 && t < LC) ? d_tmp[((size_t)bb * HID + c2) * LC + t] : 0.f;
            d_A[(size_t)m * KD + tid] = v;
            __nv_bfloat16 h = __float2bfloat16(v);
            d_Ah[(size_t)m * KD + tid] = h;
            d_Al[(size_t)m * KD + tid] = __float2bfloat16(v - __bfloat162float(h));
        }
    } else {
        int i = (b - Bq * LC) * 256 + tid;
        if (i < NL * NLAY * KD) {
            float v = ker_w[i];
            __nv_bfloat16 h = __float2bfloat16(v);
            d_Wh4[i] = h;
            d_Wl4[i] = __float2bfloat16(v - __bfloat162float(h));
        }
    }
}

// ---------------- tensor-core GEMM via mma.sync (per layer) ----------------
// C[m][n] = sum_f A[m][f]*W[n][f] + kb[n].  M=8192, N=6144, K=192.
// Weights referenced via __device__ globals + integer offset (NEVER host-passed symbols).
#define CH 64
#define PAD 8
#define STR (CH + PAD)           // 72 el, 144B row stride
#define ARR_B (128 * STR * 2)    // one array: 18432 B
#define STAGE_B (4 * ARR_B)      // 73728 B
#define GMMA_SMEM (STAGE_B + 512)

__device__ __forceinline__ void mma16816(float* d, const uint32_t* a, const uint32_t* b) {
    asm volatile(
        "mma.sync.aligned.m16n8k16.row.col.f32.bf16.bf16.f32 "
        "{%0,%1,%2,%3}, {%4,%5,%6,%7}, {%8,%9}, {%0,%1,%2,%3};"
        : "+f"(d[0]), "+f"(d[1]), "+f"(d[2]), "+f"(d[3])
        : "r"(a[0]), "r"(a[1]), "r"(a[2]), "r"(a[3]), "r"(b[0]), "r"(b[1]));
}

__global__ void __launch_bounds__(256, 2) gemm_mma(int layer, const float* __restrict__ kb) {
    extern __shared__ char smem[];
    __nv_bfloat16* sAh = (__nv_bfloat16*)smem;
    __nv_bfloat16* sAl = sAh + 128 * STR;
    __nv_bfloat16* sWh = sAl + 128 * STR;
    __nv_bfloat16* sWl = sWh + 128 * STR;
    float* kbs = (float*)(smem + STAGE_B);
    int tid = threadIdx.x, wid = tid >> 5, lane = tid & 31;
    int bm = blockIdx.y, bn = blockIdx.x;
    int wm = (wid >> 2) * 64, wn = (wid & 3) * 32;
    int gid = lane >> 2, tg = lane & 3;

    float acc[4][4][4];
#pragma unroll
    for (int i = 0; i < 4; i++)
#pragma unroll
        for (int j = 0; j < 4; j++)
#pragma unroll
            for (int q = 0; q < 4; q++) acc[i][j][q] = 0.f;

    if (tid < 128) kbs[tid] = kb[bn * 128 + tid];

    size_t wOff = (size_t)layer * NLAY * KD;
    const __nv_bfloat16* gAh = d_Ah + (size_t)(bm * 128) * KD;
    const __nv_bfloat16* gAl = d_Al + (size_t)(bm * 128) * KD;
    const __nv_bfloat16* gWh = d_Wh4 + wOff + (size_t)(bn * 128) * KD;
    const __nv_bfloat16* gWl = d_Wl4 + wOff + (size_t)(bn * 128) * KD;

    for (int c = 0; c < 3; c++) {
        __syncthreads();
#pragma unroll
        for (int i = 0; i < 4; i++) {
            int v = tid + i * 256;          // 0..1023: 128 rows x 8 x 16B
            int row = v >> 3, seg = v & 7;
            int so = row * STR + seg * 8;
            size_t go = (size_t)row * KD + c * CH + seg * 8;
            *(uint4*)(sAh + so) = *(const uint4*)(gAh + go);
            *(uint4*)(sAl + so) = *(const uint4*)(gAl + go);
            *(uint4*)(sWh + so) = *(const uint4*)(gWh + go);
            *(uint4*)(sWl + so) = *(const uint4*)(gWl + go);
        }
        __syncthreads();
#pragma unroll
        for (int ks = 0; ks < 4; ks++) {
            uint32_t afh[4][4], afl[4][4];
#pragma unroll
            for (int tm = 0; tm < 4; tm++) {
                int ro = (wm + tm * 16 + gid) * STR + ks * 16 + tg * 2;
                afh[tm][0] = *(const uint32_t*)(sAh + ro);
                afh[tm][1] = *(const uint32_t*)(sAh + ro + 8 * STR);
                afh[tm][2] = *(const uint32_t*)(sAh + ro + 8);
                afh[tm][3] = *(const uint32_t*)(sAh + ro + 8 * STR + 8);
                afl[tm][0] = *(const uint32_t*)(sAl + ro);
                afl[tm][1] = *(const uint32_t*)(sAl + ro + 8 * STR);
                afl[tm][2] = *(const uint32_t*)(sAl + ro + 8);
                afl[tm][3] = *(const uint32_t*)(sAl + ro + 8 * STR + 8);
            }
#pragma unroll
            for (int tn = 0; tn < 4; tn++) {
                int co = (wn + tn * 8 + gid) * STR + ks * 16 + tg * 2;
                uint32_t bfh[2], bfl[2];
                bfh[0] = *(const uint32_t*)(sWh + co);
                bfh[1] = *(const uint32_t*)(sWh + co + 8);
                bfl[0] = *(const uint32_t*)(sWl + co);
                bfl[1] = *(const uint32_t*)(sWl + co + 8);
#pragma unroll
                for (int tm = 0; tm < 4; tm++) {
                    mma16816(acc[tm][tn], afh[tm], bfh);
                    mma16816(acc[tm][tn], afh[tm], bfl);
                    mma16816(acc[tm][tn], afl[tm], bfh);
                }
            }
        }
    }
    __syncthreads();

    // epilogue: stage through smem for coalesced writes (reuses tile buffers)
    float* sOut = (float*)smem;        // 128x128 fp32 = 64KB < STAGE_B
#pragma unroll
    for (int tm = 0; tm < 4; tm++)
#pragma unroll
        for (int tn = 0; tn < 4; tn++) {
            int r0 = wm + tm * 16 + gid, c0 = wn + tn * 8 + tg * 2;
            sOut[r0 * 128 + c0] = acc[tm][tn][0];
            sOut[r0 * 128 + c0 + 1] = acc[tm][tn][1];
            sOut[(r0 + 8) * 128 + c0] = acc[tm][tn][2];
            sOut[(r0 + 8) * 128 + c0 + 1] = acc[tm][tn][3];
        }
    __syncthreads();
#pragma unroll
    for (int it = 0; it < 16; it++) {
        int fid = tid + it * 256;          // 0..4095 float4s
        int row = fid >> 5, cg = (fid & 31) * 4;
        float4 v = *(const float4*)(sOut + row * 128 + cg);
        v.x += kbs[cg]; v.y += kbs[cg + 1]; v.z += kbs[cg + 2]; v.w += kbs[cg + 3];
        *(float4*)(d_kern + (size_t)(bm * 128 + row) * NLAY + bn * 128 + cg) = v;
    }
}

// ---------------- bias head: kbias[m][n] = A[m] . bias_w[n] + bias_b[n] ----------------
__global__ void kbias_k(const float* __restrict__ bw, const float* __restrict__ bb) {
    __shared__ float As8[8][KD];
    int m0 = blockIdx.x * 8;
    for (int v = threadIdx.x; v < 8 * KD; v += 256)
        As8[v / KD][v % KD] = d_A[(size_t)m0 * KD + v];
    __syncthreads();
    int n = threadIdx.x;  // 256
    const float* wr = bw + n * KD;
    float b0 = bb[n];
    float acc[8];
#pragma unroll
    for (int r = 0; r < 8; r++) acc[r] = b0;
    for (int f = 0; f < KD; f++) {
        float wv = wr[f];
#pragma unroll
        for (int r = 0; r < 8; r++) acc[r] += As8[r][f] * wv;
    }
#pragma unroll
    for (int r = 0; r < 8; r++) d_kbias[(size_t)(m0 + r) * 256 + n] = acc[r];
}

// ---------------- convt_pre: lrelu + ConvTranspose1d(k=16, stride=8, pad=4) ----------------
__global__ void convt_k(const float* __restrict__ x, const float* __restrict__ w,
                        const float* __restrict__ b) {
    int idx = blockIdx.x * blockDim.x + threadIdx.x;
    if (idx >= Bq * CIN * TT) return;
    int t = idx & (TT - 1);
    int co = (idx / TT) & (CIN - 1);
    int bb = idx / (TT * CIN);
    float acc = b[co];
    int j0 = (t + 4) & 7;
#pragma unroll
    for (int jj = 0; jj < 2; jj++) {
        int j = j0 + jj * 8;
        int s = (t + 4 - j) >> 3;          // arithmetic shift: negative -> rejected
        if (s >= 0 && s < LC) {
            const float* xr = x + (size_t)bb * CIN * LC + s;
            for (int ci = 0; ci < CIN; ci++)
                acc += lrelu(xr[ci * LC]) * w[(ci * CIN + co) * 16 + j];
        }
    }
    d_xx0[idx] = acc;
}

// ---------------- fused LVC layer: dilated conv + window + einsum + gated residual ----------------
__global__ void __launch_bounds__(256) lvc_k(const float* __restrict__ cbw,
                                             const float* __restrict__ cbb,
                                             int insel, int outsel, float* __restrict__ outext,
                                             int layer, int dil) {
    __shared__ float xs[CIN][66];      // lrelu(xx) window, zero-padded
    __shared__ float ywin[CIN][12];    // lrelu(conv) at t = l*8-1 .. l*8+8 (10 used)
    __shared__ float ko[CIN * COUT * 3];
    __shared__ float osm[512];
    int l = blockIdx.x, bb = blockIdx.y, tid = threadIdx.x;
    const float* xxin = insel ? d_xx1 : d_xx0;
    float* xxout = (outsel == 2) ? outext : (outsel ? d_xx1 : d_xx0);
    size_t m = (size_t)bb * LC + l;

    const float* kp = d_kern + m * NLAY;
    for (int v = tid; v < CIN * COUT * 3; v += 256) ko[v] = kp[v];

    const float* xb = xxin + (size_t)bb * CIN * TT;
    int t0 = l * HOP - 1 - dil;
    int wlen = 10 + 2 * dil;           // <= 64 (dil=27)
    for (int v = tid; v < CIN * wlen; v += 256) {
        int ci = v / wlen, p = v - ci * wlen;
        int t = t0 + p;
        float xv = (t >= 0 && t < TT) ? xb[(size_t)ci * TT + t] : 0.f;
        xs[ci][p] = lrelu(xv);
    }
    __syncthreads();

    for (int v = tid; v < CIN * 10; v += 256) {
        int pos = v % 10, co = v / 10;
        int t = l * HOP - 1 + pos;
        float acc = cbb[co];
        const float* wr = cbw + co * CIN * 3;
        for (int ci = 0; ci < CIN; ci++) {
            acc += xs[ci][pos] * wr[ci * 3]
                 + xs[ci][pos + dil] * wr[ci * 3 + 1]
                 + xs[ci][pos + 2 * dil] * wr[ci * 3 + 2];
        }
        ywin[co][pos] = (t >= 0 && t < TT) ? lrelu(acc) : 0.f;
    }
    __syncthreads();

    for (int u = tid; u < 512; u += 256) {
        int co2 = u >> 3, h = u & 7;
        float acc = d_kbias[m * 256 + layer * 64 + co2];
        for (int ci = 0; ci < CIN; ci++) {
            const float* kc = ko + (ci * COUT + co2) * 3;
            acc += ywin[ci][h] * kc[0] + ywin[ci][h + 1] * kc[1] + ywin[ci][h + 2] * kc[2];
        }
        osm[u] = acc;
    }
    __syncthreads();

    {
        int co = tid >> 3, h = tid & 7;
        float o1 = osm[tid];
        float o2 = osm[tid + 256];
        float g = (1.f / (1.f + expf(-o1))) * tanhf(o2);
        int t = l * HOP + h;
        size_t oi = ((size_t)bb * CIN + co) * TT + t;
        xxout[oi] = xxin[oi] + g;
    }
}

// ---------------- launch ----------------
extern "C" void kernel_launch(void* const* d_in, const int* in_sizes, int n_in,
                              void* d_out, int out_size) {
    const float* x      = (const float*)d_in[0];
    const float* c      = (const float*)d_in[1];
    const float* in_w   = (const float*)d_in[2];
    const float* in_b   = (const float*)d_in[3];
    const float* res_ws = (const float*)d_in[4];
    const float* res_bs = (const float*)d_in[5];
    const float* ker_w  = (const float*)d_in[6];
    const float* ker_b  = (const float*)d_in[7];
    const float* bias_w = (const float*)d_in[8];
    const float* bias_b = (const float*)d_in[9];
    const float* ct_w   = (const float*)d_in[10];
    const float* ct_b   = (const float*)d_in[11];
    const float* cb_ws  = (const float*)d_in[12];
    const float* cb_bs  = (const float*)d_in[13];
    float* out = (float*)d_out;

    cudaFuncSetAttribute(gemm_mma, cudaFuncAttributeMaxDynamicSharedMemorySize, GMMA_SMEM);

    // launches 1-5 (so gemm layer0 is launch #6 -> gets ncu capture)
    conv_in_k<<<dim3(HID, Bq), 128>>>(c, in_w, in_b);                       // 1
    for (int j = 0; j < 3; j++) {                                           // 2,3,4
        const float* w0 = res_ws + (size_t)(j * 2) * HID * HID * 3;
        const float* w1 = res_ws + (size_t)(j * 2 + 1) * HID * HID * 3;
        // j=0: d_h->d_tmp, j=1: d_tmp->d_h, j=2: d_h->d_tmp  (prep reads d_tmp)
        res_fused_k<<<dim3(LC / RT, Bq), 256>>>(w0, res_bs + (j * 2) * HID,
                                                w1, res_bs + (j * 2 + 1) * HID, !(j & 1));
    }
    int prep_blocks = Bq * LC + (NL * NLAY * KD + 255) / 256;
    prep_k<<<prep_blocks, 256>>>(ker_w);                                    // 5

    const int dils[4] = {1, 3, 9, 27};
    gemm_mma<<<dim3(NLAY / 128, (Bq * LC) / 128), 256, GMMA_SMEM>>>(0, ker_b);  // 6 (profiled)
    convt_k<<<(Bq * CIN * TT + 255) / 256, 256>>>(x, ct_w, ct_b);           // 7
    kbias_k<<<(Bq * LC) / 8, 256>>>(bias_w, bias_b);                        // 8

    for (int i = 0; i < 4; i++) {
        if (i > 0)
            gemm_mma<<<dim3(NLAY / 128, (Bq * LC) / 128), 256, GMMA_SMEM>>>(
                i, ker_b + (size_t)i * NLAY);
        int insel = i & 1;
        int outsel = (i == 3) ? 2 : ((i + 1) & 1);
        lvc_k<<<dim3(LC, Bq), 256>>>(cb_ws + (size_t)i * CIN * CIN * 3, cb_bs + i * CIN,
                                     insel, outsel, out, i, dils[i]);
    }
}

// round 14
// speedup vs baseline: 1.1104x; 1.1104x over previous
#include <cuda_runtime.h>
#include <cuda_bf16.h>
#include <math.h>
#include <stdint.h>

#define Bq 16
#define CIN 32
#define CCOND 100
#define LC 512
#define HOP 8
#define HID 64
#define NL 4
#define COUT 64
#define TT 4096
#define KD 192          // 64*3 features for the k=3 conv-as-GEMM
#define NLAY 6144       // CIN*COUT*3 = per-layer kernel channels
#define SLOPE 0.2f

// ---------------- scratch (static __device__, no allocations) ----------------
__device__ float d_h[Bq * HID * LC];
__device__ float d_tmp[Bq * HID * LC];
__device__ float d_A[Bq * LC * KD];                    // im2col of h (fp32, for kbias)
__device__ __align__(16) __nv_bfloat16 d_Ah[Bq * LC * KD];
__device__ __align__(16) __nv_bfloat16 d_Al[Bq * LC * KD];
__device__ __align__(16) __nv_bfloat16 d_Wh4[NL * NLAY * KD];
__device__ __align__(16) __nv_bfloat16 d_Wl4[NL * NLAY * KD];
__device__ float d_kern[(size_t)Bq * LC * NLAY];       // per-layer slice [m][ci][o][k] (~201MB)
__device__ float d_kbias[Bq * LC * NL * COUT];         // [m][layer][o]
__device__ float d_xx0[Bq * CIN * TT];
__device__ float d_xx1[Bq * CIN * TT];

__device__ __forceinline__ float lrelu(float v) { return v >= 0.f ? v : SLOPE * v; }

// ---------------- kernel predictor: input conv (k=5, pad=2) + lrelu, 4 outputs/thread ----------------
__global__ void conv_in_k(const float* __restrict__ c, const float* __restrict__ w,
                          const float* __restrict__ b) {
    int co = blockIdx.x, bb = blockIdx.y;
    int l0 = threadIdx.x * 4;                     // 128 threads
    const float* cb = c + (size_t)bb * CCOND * LC;
    const float* wr = w + co * CCOND * 5;
    float a0, a1, a2, a3;
    a0 = a1 = a2 = a3 = b[co];
    for (int ci = 0; ci < CCOND; ci++) {
        const float* cr = cb + ci * LC;
        float4 xm = *(const float4*)(cr + l0);
        float xm2 = (l0 >= 2) ? cr[l0 - 2] : 0.f;
        float xm1 = (l0 >= 1) ? cr[l0 - 1] : 0.f;
        float xp4 = (l0 + 4 < LC) ? cr[l0 + 4] : 0.f;
        float xp5 = (l0 + 5 < LC) ? cr[l0 + 5] : 0.f;
        float w0 = wr[ci * 5], w1 = wr[ci * 5 + 1], w2 = wr[ci * 5 + 2],
              w3 = wr[ci * 5 + 3], w4 = wr[ci * 5 + 4];
        a0 += xm2 * w0 + xm1 * w1 + xm.x * w2 + xm.y * w3 + xm.z * w4;
        a1 += xm1 * w0 + xm.x * w1 + xm.y * w2 + xm.z * w3 + xm.w * w4;
        a2 += xm.x * w0 + xm.y * w1 + xm.z * w2 + xm.w * w3 + xp4 * w4;
        a3 += xm.y * w0 + xm.z * w1 + xm.w * w2 + xp4 * w3 + xp5 * w4;
    }
    float4 o = {lrelu(a0), lrelu(a1), lrelu(a2), lrelu(a3)};
    *(float4*)(d_h + ((size_t)bb * HID + co) * LC + l0) = o;
}

// ---------------- residual-block conv (k=3, pad=1), lrelu, optional add (R4-proven, 24us) ----------------
__global__ void conv_res_k(const float* __restrict__ w, const float* __restrict__ b,
                           int srcTmp, int dstTmp, int doAdd) {
    int co = blockIdx.x, bb = blockIdx.y;
    int l0 = threadIdx.x * 4;                     // 128 threads
    const float* in = srcTmp ? d_tmp : d_h;
    float* out = dstTmp ? d_tmp : d_h;
    const float* ib = in + (size_t)bb * HID * LC;
    const float* wr = w + co * HID * 3;
    float a0, a1, a2, a3;
    a0 = a1 = a2 = a3 = b[co];
    for (int ci = 0; ci < HID; ci++) {
        const float* xr = ib + ci * LC;
        float4 xm = *(const float4*)(xr + l0);
        float xl = (l0 >= 1) ? xr[l0 - 1] : 0.f;
        float xrg = (l0 + 4 < LC) ? xr[l0 + 4] : 0.f;
        float w0 = wr[ci * 3], w1 = wr[ci * 3 + 1], w2 = wr[ci * 3 + 2];
        a0 += xl * w0 + xm.x * w1 + xm.y * w2;
        a1 += xm.x * w0 + xm.y * w1 + xm.z * w2;
        a2 += xm.y * w0 + xm.z * w1 + xm.w * w2;
        a3 += xm.z * w0 + xm.w * w1 + xrg * w2;
    }
    float4 o = {lrelu(a0), lrelu(a1), lrelu(a2), lrelu(a3)};
    if (doAdd) {
        float4 h0 = *(const float4*)(d_h + ((size_t)bb * HID + co) * LC + l0);
        o.x += h0.x; o.y += h0.y; o.z += h0.z; o.w += h0.w;
    }
    *(float4*)(out + ((size_t)bb * HID + co) * LC + l0) = o;
}

// ---------------- prep: im2col + A hi/lo split (reads d_h) + all-layer W hi/lo split ----------------
__global__ void prep_k(const float* __restrict__ ker_w) {
    int b = blockIdx.x, tid = threadIdx.x;
    if (b < Bq * LC) {
        if (tid < KD) {
            int m = b, bb = m / LC, l = m % LC;
            int c2 = tid / 3, kk = tid % 3;
            int t = l + kk - 1;
            float v = (t >= 0 && t < LC) ? d_h[((size_t)bb * HID + c2) * LC + t] : 0.f;
            d_A[(size_t)m * KD + tid] = v;
            __nv_bfloat16 h = __float2bfloat16(v);
            d_Ah[(size_t)m * KD + tid] = h;
            d_Al[(size_t)m * KD + tid] = __float2bfloat16(v - __bfloat162float(h));
        }
    } else {
        int i = (b - Bq * LC) * 256 + tid;
        if (i < NL * NLAY * KD) {
            float v = ker_w[i];
            __nv_bfloat16 h = __float2bfloat16(v);
            d_Wh4[i] = h;
            d_Wl4[i] = __float2bfloat16(v - __bfloat162float(h));
        }
    }
}

// ---------------- tensor-core GEMM via mma.sync (per layer) — R11-passing verbatim ----------------
// C[m][n] = sum_f A[m][f]*W[n][f] + kb[n].  M=8192, N=6144, K=192.
// 128x128 tile, 8 warps, bf16 hi/lo fused 3-pass, SYNC smem loads, 2 blocks/SM,
// weights via __device__ globals + integer layer offset (NEVER host-passed symbols).
#define CH 64
#define PAD 8
#define STR (CH + PAD)           // 72 el, 144B row stride
#define ARR_B (128 * STR * 2)    // one array: 18432 B
#define STAGE_B (4 * ARR_B)      // 73728 B
#define GMMA_SMEM (STAGE_B + 512)

__device__ __forceinline__ void mma16816(float* d, const uint32_t* a, const uint32_t* b) {
    asm volatile(
        "mma.sync.aligned.m16n8k16.row.col.f32.bf16.bf16.f32 "
        "{%0,%1,%2,%3}, {%4,%5,%6,%7}, {%8,%9}, {%0,%1,%2,%3};"
        : "+f"(d[0]), "+f"(d[1]), "+f"(d[2]), "+f"(d[3])
        : "r"(a[0]), "r"(a[1]), "r"(a[2]), "r"(a[3]), "r"(b[0]), "r"(b[1]));
}

__global__ void __launch_bounds__(256, 2) gemm_mma(int layer, const float* __restrict__ kb) {
    extern __shared__ char smem[];
    __nv_bfloat16* sAh = (__nv_bfloat16*)smem;
    __nv_bfloat16* sAl = sAh + 128 * STR;
    __nv_bfloat16* sWh = sAl + 128 * STR;
    __nv_bfloat16* sWl = sWh + 128 * STR;
    float* kbs = (float*)(smem + STAGE_B);
    int tid = threadIdx.x, wid = tid >> 5, lane = tid & 31;
    int bm = blockIdx.y, bn = blockIdx.x;
    int wm = (wid >> 2) * 64, wn = (wid & 3) * 32;
    int gid = lane >> 2, tg = lane & 3;

    float acc[4][4][4];
#pragma unroll
    for (int i = 0; i < 4; i++)
#pragma unroll
        for (int j = 0; j < 4; j++)
#pragma unroll
            for (int q = 0; q < 4; q++) acc[i][j][q] = 0.f;

    if (tid < 128) kbs[tid] = kb[bn * 128 + tid];

    size_t wOff = (size_t)layer * NLAY * KD;
    const __nv_bfloat16* gAh = d_Ah + (size_t)(bm * 128) * KD;
    const __nv_bfloat16* gAl = d_Al + (size_t)(bm * 128) * KD;
    const __nv_bfloat16* gWh = d_Wh4 + wOff + (size_t)(bn * 128) * KD;
    const __nv_bfloat16* gWl = d_Wl4 + wOff + (size_t)(bn * 128) * KD;

    for (int c = 0; c < 3; c++) {
        __syncthreads();
#pragma unroll
        for (int i = 0; i < 4; i++) {
            int v = tid + i * 256;          // 0..1023: 128 rows x 8 x 16B
            int row = v >> 3, seg = v & 7;
            int so = row * STR + seg * 8;
            size_t go = (size_t)row * KD + c * CH + seg * 8;
            *(uint4*)(sAh + so) = *(const uint4*)(gAh + go);
            *(uint4*)(sAl + so) = *(const uint4*)(gAl + go);
            *(uint4*)(sWh + so) = *(const uint4*)(gWh + go);
            *(uint4*)(sWl + so) = *(const uint4*)(gWl + go);
        }
        __syncthreads();
#pragma unroll
        for (int ks = 0; ks < 4; ks++) {
            uint32_t afh[4][4], afl[4][4];
#pragma unroll
            for (int tm = 0; tm < 4; tm++) {
                int ro = (wm + tm * 16 + gid) * STR + ks * 16 + tg * 2;
                afh[tm][0] = *(const uint32_t*)(sAh + ro);
                afh[tm][1] = *(const uint32_t*)(sAh + ro + 8 * STR);
                afh[tm][2] = *(const uint32_t*)(sAh + ro + 8);
                afh[tm][3] = *(const uint32_t*)(sAh + ro + 8 * STR + 8);
                afl[tm][0] = *(const uint32_t*)(sAl + ro);
                afl[tm][1] = *(const uint32_t*)(sAl + ro + 8 * STR);
                afl[tm][2] = *(const uint32_t*)(sAl + ro + 8);
                afl[tm][3] = *(const uint32_t*)(sAl + ro + 8 * STR + 8);
            }
#pragma unroll
            for (int tn = 0; tn < 4; tn++) {
                int co = (wn + tn * 8 + gid) * STR + ks * 16 + tg * 2;
                uint32_t bfh[2], bfl[2];
                bfh[0] = *(const uint32_t*)(sWh + co);
                bfh[1] = *(const uint32_t*)(sWh + co + 8);
                bfl[0] = *(const uint32_t*)(sWl + co);
                bfl[1] = *(const uint32_t*)(sWl + co + 8);
#pragma unroll
                for (int tm = 0; tm < 4; tm++) {
                    mma16816(acc[tm][tn], afh[tm], bfh);
                    mma16816(acc[tm][tn], afh[tm], bfl);
                    mma16816(acc[tm][tn], afl[tm], bfh);
                }
            }
        }
    }
    __syncthreads();

    // epilogue: stage through smem for coalesced writes (reuses tile buffers)
    float* sOut = (float*)smem;        // 128x128 fp32 = 64KB < STAGE_B
#pragma unroll
    for (int tm = 0; tm < 4; tm++)
#pragma unroll
        for (int tn = 0; tn < 4; tn++) {
            int r0 = wm + tm * 16 + gid, c0 = wn + tn * 8 + tg * 2;
            sOut[r0 * 128 + c0] = acc[tm][tn][0];
            sOut[r0 * 128 + c0 + 1] = acc[tm][tn][1];
            sOut[(r0 + 8) * 128 + c0] = acc[tm][tn][2];
            sOut[(r0 + 8) * 128 + c0 + 1] = acc[tm][tn][3];
        }
    __syncthreads();
#pragma unroll
    for (int it = 0; it < 16; it++) {
        int fid = tid + it * 256;          // 0..4095 float4s
        int row = fid >> 5, cg = (fid & 31) * 4;
        float4 v = *(const float4*)(sOut + row * 128 + cg);
        v.x += kbs[cg]; v.y += kbs[cg + 1]; v.z += kbs[cg + 2]; v.w += kbs[cg + 3];
        *(float4*)(d_kern + (size_t)(bm * 128 + row) * NLAY + bn * 128 + cg) = v;
    }
}

// ---------------- bias head: kbias[m][n] = A[m] . bias_w[n] + bias_b[n] ----------------
__global__ void kbias_k(const float* __restrict__ bw, const float* __restrict__ bb) {
    __shared__ float As8[8][KD];
    int m0 = blockIdx.x * 8;
    for (int v = threadIdx.x; v < 8 * KD; v += 256)
        As8[v / KD][v % KD] = d_A[(size_t)m0 * KD + v];
    __syncthreads();
    int n = threadIdx.x;  // 256
    const float* wr = bw + n * KD;
    float b0 = bb[n];
    float acc[8];
#pragma unroll
    for (int r = 0; r < 8; r++) acc[r] = b0;
    for (int f = 0; f < KD; f++) {
        float wv = wr[f];
#pragma unroll
        for (int r = 0; r < 8; r++) acc[r] += As8[r][f] * wv;
    }
#pragma unroll
    for (int r = 0; r < 8; r++) d_kbias[(size_t)(m0 + r) * 256 + n] = acc[r];
}

// ---------------- convt_pre: lrelu + ConvTranspose1d(k=16, stride=8, pad=4) ----------------
__global__ void convt_k(const float* __restrict__ x, const float* __restrict__ w,
                        const float* __restrict__ b) {
    int idx = blockIdx.x * blockDim.x + threadIdx.x;
    if (idx >= Bq * CIN * TT) return;
    int t = idx & (TT - 1);
    int co = (idx / TT) & (CIN - 1);
    int bb = idx / (TT * CIN);
    float acc = b[co];
    int j0 = (t + 4) & 7;
#pragma unroll
    for (int jj = 0; jj < 2; jj++) {
        int j = j0 + jj * 8;
        int s = (t + 4 - j) >> 3;          // arithmetic shift: negative -> rejected
        if (s >= 0 && s < LC) {
            const float* xr = x + (size_t)bb * CIN * LC + s;
            for (int ci = 0; ci < CIN; ci++)
                acc += lrelu(xr[ci * LC]) * w[(ci * CIN + co) * 16 + j];
        }
    }
    d_xx0[idx] = acc;
}

// ---------------- fused LVC layer: dilated conv + window + einsum + gated residual ----------------
__global__ void __launch_bounds__(256) lvc_k(const float* __restrict__ cbw,
                                             const float* __restrict__ cbb,
                                             int insel, int outsel, float* __restrict__ outext,
                                             int layer, int dil) {
    __shared__ float xs[CIN][66];      // lrelu(xx) window, zero-padded
    __shared__ float ywin[CIN][12];    // lrelu(conv) at t = l*8-1 .. l*8+8 (10 used)
    __shared__ float ko[CIN * COUT * 3];
    __shared__ float osm[512];
    int l = blockIdx.x, bb = blockIdx.y, tid = threadIdx.x;
    const float* xxin = insel ? d_xx1 : d_xx0;
    float* xxout = (outsel == 2) ? outext : (outsel ? d_xx1 : d_xx0);
    size_t m = (size_t)bb * LC + l;

    const float* kp = d_kern + m * NLAY;
    for (int v = tid; v < CIN * COUT * 3; v += 256) ko[v] = kp[v];

    const float* xb = xxin + (size_t)bb * CIN * TT;
    int t0 = l * HOP - 1 - dil;
    int wlen = 10 + 2 * dil;           // <= 64 (dil=27)
    for (int v = tid; v < CIN * wlen; v += 256) {
        int ci = v / wlen, p = v - ci * wlen;
        int t = t0 + p;
        float xv = (t >= 0 && t < TT) ? xb[(size_t)ci * TT + t] : 0.f;
        xs[ci][p] = lrelu(xv);
    }
    __syncthreads();

    for (int v = tid; v < CIN * 10; v += 256) {
        int pos = v % 10, co = v / 10;
        int t = l * HOP - 1 + pos;
        float acc = cbb[co];
        const float* wr = cbw + co * CIN * 3;
        for (int ci = 0; ci < CIN; ci++) {
            acc += xs[ci][pos] * wr[ci * 3]
                 + xs[ci][pos + dil] * wr[ci * 3 + 1]
                 + xs[ci][pos + 2 * dil] * wr[ci * 3 + 2];
        }
        ywin[co][pos] = (t >= 0 && t < TT) ? lrelu(acc) : 0.f;
    }
    __syncthreads();

    for (int u = tid; u < 512; u += 256) {
        int co2 = u >> 3, h = u & 7;
        float acc = d_kbias[m * 256 + layer * 64 + co2];
        for (int ci = 0; ci < CIN; ci++) {
            const float* kc = ko + (ci * COUT + co2) * 3;
            acc += ywin[ci][h] * kc[0] + ywin[ci][h + 1] * kc[1] + ywin[ci][h + 2] * kc[2];
        }
        osm[u] = acc;
    }
    __syncthreads();

    {
        int co = tid >> 3, h = tid & 7;
        float o1 = osm[tid];
        float o2 = osm[tid + 256];
        float g = (1.f / (1.f + expf(-o1))) * tanhf(o2);
        int t = l * HOP + h;
        size_t oi = ((size_t)bb * CIN + co) * TT + t;
        xxout[oi] = xxin[oi] + g;
    }
}

// ---------------- launch ----------------
extern "C" void kernel_launch(void* const* d_in, const int* in_sizes, int n_in,
                              void* d_out, int out_size) {
    const float* x      = (const float*)d_in[0];
    const float* c      = (const float*)d_in[1];
    const float* in_w   = (const float*)d_in[2];
    const float* in_b   = (const float*)d_in[3];
    const float* res_ws = (const float*)d_in[4];
    const float* res_bs = (const float*)d_in[5];
    const float* ker_w  = (const float*)d_in[6];
    const float* ker_b  = (const float*)d_in[7];
    const float* bias_w = (const float*)d_in[8];
    const float* bias_b = (const float*)d_in[9];
    const float* ct_w   = (const float*)d_in[10];
    const float* ct_b   = (const float*)d_in[11];
    const float* cb_ws  = (const float*)d_in[12];
    const float* cb_bs  = (const float*)d_in[13];
    float* out = (float*)d_out;

    cudaFuncSetAttribute(gemm_mma, cudaFuncAttributeMaxDynamicSharedMemorySize, GMMA_SMEM);

    conv_in_k<<<dim3(HID, Bq), 128>>>(c, in_w, in_b);
    for (int j = 0; j < 3; j++) {
        conv_res_k<<<dim3(HID, Bq), 128>>>(res_ws + (size_t)(j * 2) * HID * HID * 3,
                                           res_bs + (j * 2) * HID, 0, 1, 0);
        conv_res_k<<<dim3(HID, Bq), 128>>>(res_ws + (size_t)(j * 2 + 1) * HID * HID * 3,
                                           res_bs + (j * 2 + 1) * HID, 1, 0, 1);
    }
    int prep_blocks = Bq * LC + (NL * NLAY * KD + 255) / 256;
    prep_k<<<prep_blocks, 256>>>(ker_w);
    kbias_k<<<(Bq * LC) / 8, 256>>>(bias_w, bias_b);
    convt_k<<<(Bq * CIN * TT + 255) / 256, 256>>>(x, ct_w, ct_b);

    const int dils[4] = {1, 3, 9, 27};
    for (int i = 0; i < 4; i++) {
        gemm_mma<<<dim3(NLAY / 128, (Bq * LC) / 128), 256, GMMA_SMEM>>>(i, ker_b + (size_t)i * NLAY);
        int insel = i & 1;
        int outsel = (i == 3) ? 2 : ((i + 1) & 1);
        lvc_k<<<dim3(LC, Bq), 256>>>(cb_ws + (size_t)i * CIN * CIN * 3, cb_bs + i * CIN,
                                     insel, outsel, out, i, dils[i]);
    }
}